// round 5
// baseline (speedup 1.0000x reference)
#include <cuda_runtime.h>
#include <cuda_bf16.h>
#include <math.h>

#define BB 16
#define PP 19248
#define NOBJ 32
#define NC 81
#define POS_TH 0.5f
#define NEG_TH 0.4f

__device__ float              g_negval[BB * PP];
__device__ unsigned long long g_ovgt[BB * PP];     // (ov_bits << 32) | gt_idx
__device__ unsigned long long g_bestkey[BB * NOBJ];
__device__ float g_loss_l;
__device__ float g_loss_c;
__device__ int   g_npos[BB];
__device__ int   g_total_pos;
__device__ int   g_done;

__global__ void init_kernel() {
    int t = threadIdx.x;
    if (t == 0) {
        g_loss_l = 0.f;
        g_loss_c = 0.f;
        g_total_pos = 0;
        g_done = 0;
    }
    if (t < BB) g_npos[t] = 0;
    if (t < BB * NOBJ) g_bestkey[t] = 0ull;
}

// -------- Kernel 1: IoU pass. one warp handles 8 priors; lane n = gt n --------
__global__ void iou_kernel(const float* __restrict__ priors,
                           const float* __restrict__ gt_boxes) {
    const int b = blockIdx.y;
    const int warp = threadIdx.x >> 5;
    const int lane = threadIdx.x & 31;

    __shared__ float4             sgt[NOBJ];
    __shared__ unsigned long long skey[NOBJ];
    if (threadIdx.x < NOBJ) {
        sgt[threadIdx.x]  = ((const float4*)gt_boxes)[b * NOBJ + threadIdx.x];
        skey[threadIdx.x] = 0ull;
    }
    __syncthreads();

    float4 g = sgt[lane];
    float area_g = (g.z - g.x) * (g.w - g.y);
    unsigned long long mykey = 0ull;
    unsigned long long myres = 0ull;

    int base = blockIdx.x * 64 + warp * 8;
#pragma unroll
    for (int k = 0; k < 8; k++) {
        int p = base + k;
        if (p >= PP) break;
        float4 pr = ((const float4*)priors)[p];
        float px1 = pr.x - pr.z * 0.5f, py1 = pr.y - pr.w * 0.5f;
        float px2 = pr.x + pr.z * 0.5f, py2 = pr.y + pr.w * 0.5f;
        float area_p = (px2 - px1) * (py2 - py1);

        float lx = fmaxf(g.x, px1), ly = fmaxf(g.y, py1);
        float rx = fminf(g.z, px2), ry = fminf(g.w, py2);
        float w = fmaxf(rx - lx, 0.f), h = fmaxf(ry - ly, 0.f);
        float inter = w * h;
        float ov = inter / (area_g + area_p - inter);   // IEEE div, matches ref

        // per-gt best prior: max ov, tie -> lowest p
        unsigned long long key =
            ((unsigned long long)__float_as_uint(ov) << 32) |
            (unsigned long long)(0xFFFFFFFFu - (unsigned)p);
        mykey = (key > mykey) ? key : mykey;

        // per-prior best gt: max ov, tie -> lowest gt index (ov >= 0 so
        // uint order == float order; ffs of ballot = lowest lane)
        unsigned ovb = __float_as_uint(ov);
        unsigned umax = __reduce_max_sync(0xffffffffu, ovb);
        unsigned bal = __ballot_sync(0xffffffffu, ovb == umax);
        if (lane == k)  // results are warp-uniform; lane k keeps prior k's
            myres = ((unsigned long long)umax << 32) |
                    (unsigned long long)(__ffs(bal) - 1);
    }
    if (lane < 8 && base + lane < PP)
        g_ovgt[(size_t)b * PP + base + lane] = myres;   // coalesced 64B burst

    atomicMax(&skey[lane], mykey);
    __syncthreads();
    if (threadIdx.x < NOBJ)
        atomicMax(&g_bestkey[b * NOBJ + threadIdx.x], skey[threadIdx.x]);
}

// -------- Kernel 2: NLL + match resolution + loc loss (smem-staged conf) --------
#define NLL_PRIORS 48   // PP = 48 * 401 exactly
#define NLL_THREADS 512 // 16 warps * 3 priors

__global__ void nll_kernel(const float* __restrict__ loc_data,
                           const float* __restrict__ conf_data,
                           const float* __restrict__ priors,
                           const float* __restrict__ gt_boxes,
                           const int*   __restrict__ gt_labels) {
    const int b = blockIdx.y;
    const int warp = threadIdx.x >> 5;
    const int lane = threadIdx.x & 31;
    const int p0 = blockIdx.x * NLL_PRIORS;

    __shared__ float  sconf[NLL_PRIORS * NC];
    __shared__ float  snv[NLL_PRIORS];
    __shared__ float4 sgt[NOBJ];
    __shared__ int    slab[NOBJ];
    __shared__ int    sbp[NOBJ];
    if (threadIdx.x < NOBJ) {
        sgt[threadIdx.x]  = ((const float4*)gt_boxes)[b * NOBJ + threadIdx.x];
        slab[threadIdx.x] = gt_labels[b * NOBJ + threadIdx.x];
        unsigned long long k = g_bestkey[b * NOBJ + threadIdx.x];
        sbp[threadIdx.x] = (int)(0xFFFFFFFFu - (unsigned)(k & 0xFFFFFFFFull));
    }

    // prefetch this warp's 3 match results early (lanes 0..2)
    unsigned long long myovgt = 0ull;
    const int pbase = p0 + warp * 3;
    if (lane < 3)
        myovgt = g_ovgt[(size_t)b * PP + pbase + lane];

    // coalesced float4 stage of 48 contiguous priors' logits
    const float4* src = (const float4*)(conf_data + ((size_t)b * PP + p0) * NC);
#pragma unroll
    for (int i = threadIdx.x; i < NLL_PRIORS * NC / 4; i += NLL_THREADS)
        ((float4*)sconf)[i] = src[i];
    __syncthreads();

#pragma unroll
    for (int j = 0; j < 3; j++) {
        int q = warp * 3 + j;
        int p = p0 + q;

        const float* row = sconf + q * NC;
        float v0 = row[lane];
        float v1 = row[lane + 32];
        float v2 = (lane < NC - 64) ? row[lane + 64] : -INFINITY;
        float m = fmaxf(fmaxf(v0, v1), v2);
#pragma unroll
        for (int off = 16; off > 0; off >>= 1)
            m = fmaxf(m, __shfl_xor_sync(0xffffffffu, m, off));
        float s = __expf(v0 - m) + __expf(v1 - m) +
                  ((lane < NC - 64) ? __expf(v2 - m) : 0.f);
#pragma unroll
        for (int off = 16; off > 0; off >>= 1)
            s += __shfl_xor_sync(0xffffffffu, s, off);

        unsigned mask = __ballot_sync(0xffffffffu, sbp[lane] == p);
        unsigned long long og = __shfl_sync(0xffffffffu, myovgt, j);

        if (lane == 0) {
            float ov = __uint_as_float((unsigned)(og >> 32));
            int   idx = (int)(unsigned)og;
            if (mask) { idx = 31 - __clz(mask); ov = 2.0f; }

            int conf_t;
            if (ov < NEG_TH)      conf_t = 0;
            else if (ov < POS_TH) conf_t = -1;
            else                  conf_t = slab[idx] + 1;

            float lse = m + __logf(s);
            int ct = conf_t > 0 ? conf_t : 0;
            float nll = lse - row[ct];
            snv[q] = (conf_t == 0) ? nll : 0.f;

            if (conf_t > 0) {
                atomicAdd(&g_loss_c, nll);
                atomicAdd(&g_npos[b], 1);
                atomicAdd(&g_total_pos, 1);
                float4 pr = ((const float4*)priors)[p];
                float4 gt = sgt[idx];
                float mcx = (gt.x + gt.z) * 0.5f;
                float mcy = (gt.y + gt.w) * 0.5f;
                float mw  = gt.z - gt.x;
                float mh  = gt.w - gt.y;
                float t0 = (mcx - pr.x) / (0.1f * pr.z);
                float t1 = (mcy - pr.y) / (0.1f * pr.w);
                float t2 = logf(mw / pr.z) / 0.2f;
                float t3 = logf(mh / pr.w) / 0.2f;
                float4 ld = ((const float4*)loc_data)[(size_t)b * PP + p];
                float acc = 0.f, d, ad;
                d = ld.x - t0; ad = fabsf(d); acc += (ad < 1.f) ? 0.5f * d * d : ad - 0.5f;
                d = ld.y - t1; ad = fabsf(d); acc += (ad < 1.f) ? 0.5f * d * d : ad - 0.5f;
                d = ld.z - t2; ad = fabsf(d); acc += (ad < 1.f) ? 0.5f * d * d : ad - 0.5f;
                d = ld.w - t3; ad = fabsf(d); acc += (ad < 1.f) ? 0.5f * d * d : ad - 0.5f;
                atomicAdd(&g_loss_l, acc);
            }
        }
    }
    __syncthreads();
    if (threadIdx.x < NLL_PRIORS)   // coalesced negval write
        g_negval[(size_t)b * PP + p0 + threadIdx.x] = snv[threadIdx.x];
}

// -------- Kernel 3: hard negative mining + finalize --------
#define BUFSZ 6144
extern __shared__ float sv[];  // PP floats

__device__ __forceinline__ int warp_suffix(int v, int lane) {
#pragma unroll
    for (int off = 1; off < 32; off <<= 1) {
        int t = __shfl_down_sync(0xffffffffu, v, off);
        if (lane + off < 32) v += t;
    }
    return v;
}

// two-level bin finder over hist[nb]; all threads participate.
// outputs: sB = bin containing the Krem-th largest, sK = remaining inside it
__device__ __forceinline__ void find_bin(int* hist, int nb, int Krem,
                                         int tid, int lane, int warpId,
                                         int* s_seg, int* psWstar,
                                         int* psB, int* psK) {
    int nsegs = nb >> 6;
    if (warpId < nsegs) {
        int base = warpId * 64;
        int s = hist[base + lane] + hist[base + 32 + lane];
        s = (int)__reduce_add_sync(0xffffffffu, (unsigned)s);
        if (lane == 0) s_seg[warpId] = s;
    }
    __syncthreads();
    if (tid < 32) {
        int v = (lane < nsegs) ? s_seg[lane] : 0;
        int ssum = warp_suffix(v, lane);
        unsigned bal = __ballot_sync(0xffffffffu, ssum >= Krem);
        int w = 31 - __clz(bal);
        int ssum_w = __shfl_sync(0xffffffffu, ssum, w);
        int v_w    = __shfl_sync(0xffffffffu, v, w);
        if (lane == 0) { *psWstar = w; *psK = Krem - (ssum_w - v_w); }
    }
    __syncthreads();
    if (warpId == *psWstar) {
        int base = warpId * 64;
        int K2 = *psK;
        int h1 = hist[base + 32 + lane];
        int s1 = warp_suffix(h1, lane);
        int tot1 = __shfl_sync(0xffffffffu, s1, 0);
        int bin, Kn;
        if (K2 <= tot1) {
            unsigned bal = __ballot_sync(0xffffffffu, s1 >= K2);
            int l = 31 - __clz(bal);
            bin = base + 32 + l;
            Kn = K2 - (__shfl_sync(0xffffffffu, s1, l) -
                       __shfl_sync(0xffffffffu, h1, l));
        } else {
            int K3 = K2 - tot1;
            int h0 = hist[base + lane];
            int s0 = warp_suffix(h0, lane);
            unsigned bal = __ballot_sync(0xffffffffu, s0 >= K3);
            int l = 31 - __clz(bal);
            bin = base + l;
            Kn = K3 - (__shfl_sync(0xffffffffu, s0, l) -
                       __shfl_sync(0xffffffffu, h0, l));
        }
        if (lane == 0) { *psB = bin; *psK = Kn; }
    }
    __syncthreads();
}

__global__ void mine_kernel(float* __restrict__ out) {
    const int b = blockIdx.x;
    const int tid = threadIdx.x;
    const int lane = tid & 31;
    const int warpId = tid >> 5;
    const int K = min(3 * g_npos[b], PP - 1);

    __shared__ int   hist[2048];
    __shared__ float sbuf[BUFSZ];
    __shared__ int   s_seg[32];
    __shared__ int   s_nbuf, sWstar, sB, sK, s_cnt, s_cnt2;
    __shared__ float s_sum, s_sum2;

    if (K > 0) {
        const float* vals = g_negval + (size_t)b * PP;

        // sweep 1: load sv + 2048-bin histogram of top-11 bits (fused)
        for (int i = tid; i < 2048; i += 1024) hist[i] = 0;
        if (tid == 0) {
            s_nbuf = 0; s_cnt = 0; s_sum = 0.f; s_cnt2 = 0; s_sum2 = 0.f;
        }
        __syncthreads();
        for (int p = tid; p < PP; p += 1024) {
            float v = vals[p];
            sv[p] = v;
            atomicAdd(&hist[__float_as_uint(v) >> 20], 1);
        }
        __syncthreads();

        find_bin(hist, 2048, K, tid, lane, warpId, s_seg, &sWstar, &sB, &sK);
        const int B1 = sB;
        int Krem = sK;
        __syncthreads();

        // sweep 2: sum bins > B1; collect boundary-bin elements
        int cgt = 0;
        float sum = 0.f;
        for (int p = tid; p < PP; p += 1024) {
            float v = sv[p];
            int bin = (int)(__float_as_uint(v) >> 20);
            if (bin > B1) { cgt++; sum += v; }
            else if (bin == B1) {
                int i = atomicAdd(&s_nbuf, 1);
                if (i < BUFSZ) sbuf[i] = v;
            }
        }
#pragma unroll
        for (int off = 16; off > 0; off >>= 1) {
            cgt += __shfl_down_sync(0xffffffffu, cgt, off);
            sum += __shfl_down_sync(0xffffffffu, sum, off);
        }
        if (lane == 0) { atomicAdd(&s_cnt, cgt); atomicAdd(&s_sum, sum); }
        __syncthreads();

        const int  nB = s_nbuf;
        const bool usebuf = (nB <= BUFSZ);

        // refine remaining 21 bits exactly on the boundary set
        unsigned prefix = (unsigned)B1 << 20;
        unsigned himask = 0xFFFFFFFFu << 20;
        const int shifts2[2] = {9, 0};
        const int nbs2[2]    = {2048, 512};
        for (int st = 0; st < 2; st++) {
            int shift = shifts2[st], nb = nbs2[st];
            for (int i = tid; i < nb; i += 1024) hist[i] = 0;
            __syncthreads();
            if (usebuf) {
                for (int i = tid; i < nB; i += 1024) {
                    unsigned u = __float_as_uint(sbuf[i]);
                    if ((u & himask) == prefix)
                        atomicAdd(&hist[(u >> shift) & (nb - 1)], 1);
                }
            } else {
                for (int p = tid; p < PP; p += 1024) {
                    unsigned u = __float_as_uint(sv[p]);
                    if ((u & himask) == prefix)
                        atomicAdd(&hist[(u >> shift) & (nb - 1)], 1);
                }
            }
            __syncthreads();
            find_bin(hist, nb, Krem, tid, lane, warpId, s_seg, &sWstar, &sB, &sK);
            prefix |= ((unsigned)sB) << shift;
            himask |= ((unsigned)(nb - 1)) << shift;
            Krem = sK;
            __syncthreads();
        }

        // boundary pass: strictly greater than exact threshold, within bin B1
        float t = __uint_as_float(prefix);
        int cgt2 = 0;
        float sum2 = 0.f;
        if (usebuf) {
            for (int i = tid; i < nB; i += 1024) {
                float v = sbuf[i];
                if (__float_as_uint(v) > prefix) { cgt2++; sum2 += v; }
            }
        } else {
            for (int p = tid; p < PP; p += 1024) {
                float v = sv[p];
                unsigned u = __float_as_uint(v);
                if ((int)(u >> 20) == B1 && u > prefix) { cgt2++; sum2 += v; }
            }
        }
#pragma unroll
        for (int off = 16; off > 0; off >>= 1) {
            cgt2 += __shfl_down_sync(0xffffffffu, cgt2, off);
            sum2 += __shfl_down_sync(0xffffffffu, sum2, off);
        }
        if (lane == 0) { atomicAdd(&s_cnt2, cgt2); atomicAdd(&s_sum2, sum2); }
        __syncthreads();

        if (tid == 0) {
            float total = s_sum + s_sum2 +
                          (float)(K - s_cnt - s_cnt2) * t;
            atomicAdd(&g_loss_c, total);
        }
    }

    // finalize: last block writes the output
    if (tid == 0) {
        __threadfence();
        int old = atomicAdd(&g_done, 1);
        if (old == BB - 1) {
            float lc = atomicAdd(&g_loss_c, 0.f);
            float ll = atomicAdd(&g_loss_l, 0.f);
            int   tp = atomicAdd(&g_total_pos, 0);
            float N = (float)max(tp, 1);
            out[0] = ll / N;
            out[1] = lc / N;
        }
    }
}

extern "C" void kernel_launch(void* const* d_in, const int* in_sizes, int n_in,
                              void* d_out, int out_size) {
    const float* loc_data  = (const float*)d_in[0];
    const float* conf_data = (const float*)d_in[1];
    const float* priors    = (const float*)d_in[2];
    const float* gt_boxes  = (const float*)d_in[3];
    const int*   gt_labels = (const int*)d_in[4];
    float* out = (float*)d_out;

    cudaFuncSetAttribute(mine_kernel,
                         cudaFuncAttributeMaxDynamicSharedMemorySize,
                         PP * (int)sizeof(float));

    init_kernel<<<1, BB * NOBJ>>>();
    dim3 gridI((PP + 63) / 64, BB);
    iou_kernel<<<gridI, 256>>>(priors, gt_boxes);
    dim3 gridN(PP / NLL_PRIORS, BB);
    nll_kernel<<<gridN, NLL_THREADS>>>(loc_data, conf_data, priors, gt_boxes, gt_labels);
    mine_kernel<<<BB, 1024, PP * (int)sizeof(float)>>>(out);
}

// round 6
// speedup vs baseline: 1.0149x; 1.0149x over previous
#include <cuda_runtime.h>
#include <cuda_bf16.h>
#include <math.h>

#define BB 16
#define PP 19248
#define NOBJ 32
#define NC 81
#define POS_TH 0.5f
#define NEG_TH 0.4f

__device__ float              g_negval[BB * PP];
__device__ unsigned long long g_ovgt[BB * PP];     // (ov_bits << 32) | gt_idx
__device__ unsigned long long g_bestkey[BB * NOBJ];
__device__ float g_loss_l;
__device__ float g_loss_c;
__device__ int   g_npos[BB];
__device__ int   g_total_pos;
__device__ int   g_done;

__global__ void init_kernel() {
    int t = threadIdx.x;
    if (t == 0) {
        g_loss_l = 0.f;
        g_loss_c = 0.f;
        g_total_pos = 0;
        g_done = 0;
    }
    if (t < BB) g_npos[t] = 0;
    if (t < BB * NOBJ) g_bestkey[t] = 0ull;
}

// -------- Kernel 1: IoU pass. one warp handles 8 priors; lane n = gt n --------
__global__ void iou_kernel(const float* __restrict__ priors,
                           const float* __restrict__ gt_boxes) {
    const int b = blockIdx.y;
    const int warp = threadIdx.x >> 5;
    const int lane = threadIdx.x & 31;

    __shared__ float4             sgt[NOBJ];
    __shared__ unsigned long long skey[NOBJ];
    if (threadIdx.x < NOBJ) {
        sgt[threadIdx.x]  = ((const float4*)gt_boxes)[b * NOBJ + threadIdx.x];
        skey[threadIdx.x] = 0ull;
    }
    __syncthreads();

    float4 g = sgt[lane];
    float area_g = (g.z - g.x) * (g.w - g.y);
    unsigned long long mykey = 0ull;
    unsigned long long myres = 0ull;

    int base = blockIdx.x * 64 + warp * 8;
#pragma unroll
    for (int k = 0; k < 8; k++) {
        int p = base + k;
        if (p >= PP) break;
        float4 pr = ((const float4*)priors)[p];
        float px1 = pr.x - pr.z * 0.5f, py1 = pr.y - pr.w * 0.5f;
        float px2 = pr.x + pr.z * 0.5f, py2 = pr.y + pr.w * 0.5f;
        float area_p = (px2 - px1) * (py2 - py1);

        float lx = fmaxf(g.x, px1), ly = fmaxf(g.y, py1);
        float rx = fminf(g.z, px2), ry = fminf(g.w, py2);
        float w = fmaxf(rx - lx, 0.f), h = fmaxf(ry - ly, 0.f);
        float inter = w * h;
        float ov = inter / (area_g + area_p - inter);   // IEEE div, matches ref

        // per-gt best prior: max ov, tie -> lowest p
        unsigned long long key =
            ((unsigned long long)__float_as_uint(ov) << 32) |
            (unsigned long long)(0xFFFFFFFFu - (unsigned)p);
        mykey = (key > mykey) ? key : mykey;

        // per-prior best gt: max ov, tie -> lowest gt index (ov >= 0 so
        // uint order == float order; ffs of ballot = lowest lane)
        unsigned ovb = __float_as_uint(ov);
        unsigned umax = __reduce_max_sync(0xffffffffu, ovb);
        unsigned bal = __ballot_sync(0xffffffffu, ovb == umax);
        if (lane == k)  // results are warp-uniform; lane k keeps prior k's
            myres = ((unsigned long long)umax << 32) |
                    (unsigned long long)(__ffs(bal) - 1);
    }
    if (lane < 8 && base + lane < PP)
        g_ovgt[(size_t)b * PP + base + lane] = myres;   // coalesced 64B burst

    atomicMax(&skey[lane], mykey);
    __syncthreads();
    if (threadIdx.x < NOBJ)
        atomicMax(&g_bestkey[b * NOBJ + threadIdx.x], skey[threadIdx.x]);
}

// -------- Kernel 2: NLL + match resolution + loc loss (smem-staged conf) --------
#define NLL_PRIORS 48   // PP = 48 * 401 exactly
#define NLL_THREADS 512 // 16 warps * 3 priors

__global__ void nll_kernel(const float* __restrict__ loc_data,
                           const float* __restrict__ conf_data,
                           const float* __restrict__ priors,
                           const float* __restrict__ gt_boxes,
                           const int*   __restrict__ gt_labels) {
    const int b = blockIdx.y;
    const int warp = threadIdx.x >> 5;
    const int lane = threadIdx.x & 31;
    const int p0 = blockIdx.x * NLL_PRIORS;

    __shared__ float  sconf[NLL_PRIORS * NC];
    __shared__ float  snv[NLL_PRIORS];
    __shared__ float4 sgt[NOBJ];
    __shared__ int    slab[NOBJ];
    __shared__ int    sbp[NOBJ];
    if (threadIdx.x < NOBJ) {
        sgt[threadIdx.x]  = ((const float4*)gt_boxes)[b * NOBJ + threadIdx.x];
        slab[threadIdx.x] = gt_labels[b * NOBJ + threadIdx.x];
        unsigned long long k = g_bestkey[b * NOBJ + threadIdx.x];
        sbp[threadIdx.x] = (int)(0xFFFFFFFFu - (unsigned)(k & 0xFFFFFFFFull));
    }

    // prefetch this warp's 3 match results early (lanes 0..2)
    unsigned long long myovgt = 0ull;
    const int pbase = p0 + warp * 3;
    if (lane < 3)
        myovgt = g_ovgt[(size_t)b * PP + pbase + lane];

    // coalesced float4 stage of 48 contiguous priors' logits
    const float4* src = (const float4*)(conf_data + ((size_t)b * PP + p0) * NC);
#pragma unroll
    for (int i = threadIdx.x; i < NLL_PRIORS * NC / 4; i += NLL_THREADS)
        ((float4*)sconf)[i] = src[i];
    __syncthreads();

#pragma unroll
    for (int j = 0; j < 3; j++) {
        int q = warp * 3 + j;
        int p = p0 + q;

        const float* row = sconf + q * NC;
        float v0 = row[lane];
        float v1 = row[lane + 32];
        float v2 = (lane < NC - 64) ? row[lane + 64] : -INFINITY;
        float m = fmaxf(fmaxf(v0, v1), v2);
#pragma unroll
        for (int off = 16; off > 0; off >>= 1)
            m = fmaxf(m, __shfl_xor_sync(0xffffffffu, m, off));
        float s = __expf(v0 - m) + __expf(v1 - m) +
                  ((lane < NC - 64) ? __expf(v2 - m) : 0.f);
#pragma unroll
        for (int off = 16; off > 0; off >>= 1)
            s += __shfl_xor_sync(0xffffffffu, s, off);

        unsigned mask = __ballot_sync(0xffffffffu, sbp[lane] == p);
        unsigned long long og = __shfl_sync(0xffffffffu, myovgt, j);

        if (lane == 0) {
            float ov = __uint_as_float((unsigned)(og >> 32));
            int   idx = (int)(unsigned)og;
            if (mask) { idx = 31 - __clz(mask); ov = 2.0f; }

            int conf_t;
            if (ov < NEG_TH)      conf_t = 0;
            else if (ov < POS_TH) conf_t = -1;
            else                  conf_t = slab[idx] + 1;

            float lse = m + __logf(s);
            int ct = conf_t > 0 ? conf_t : 0;
            float nll = lse - row[ct];
            snv[q] = (conf_t == 0) ? nll : 0.f;

            if (conf_t > 0) {
                atomicAdd(&g_loss_c, nll);
                atomicAdd(&g_npos[b], 1);
                atomicAdd(&g_total_pos, 1);
                float4 pr = ((const float4*)priors)[p];
                float4 gt = sgt[idx];
                float mcx = (gt.x + gt.z) * 0.5f;
                float mcy = (gt.y + gt.w) * 0.5f;
                float mw  = gt.z - gt.x;
                float mh  = gt.w - gt.y;
                float t0 = (mcx - pr.x) / (0.1f * pr.z);
                float t1 = (mcy - pr.y) / (0.1f * pr.w);
                float t2 = logf(mw / pr.z) / 0.2f;
                float t3 = logf(mh / pr.w) / 0.2f;
                float4 ld = ((const float4*)loc_data)[(size_t)b * PP + p];
                float acc = 0.f, d, ad;
                d = ld.x - t0; ad = fabsf(d); acc += (ad < 1.f) ? 0.5f * d * d : ad - 0.5f;
                d = ld.y - t1; ad = fabsf(d); acc += (ad < 1.f) ? 0.5f * d * d : ad - 0.5f;
                d = ld.z - t2; ad = fabsf(d); acc += (ad < 1.f) ? 0.5f * d * d : ad - 0.5f;
                d = ld.w - t3; ad = fabsf(d); acc += (ad < 1.f) ? 0.5f * d * d : ad - 0.5f;
                atomicAdd(&g_loss_l, acc);
            }
        }
    }
    __syncthreads();
    if (threadIdx.x < NLL_PRIORS)   // coalesced negval write
        g_negval[(size_t)b * PP + p0 + threadIdx.x] = snv[threadIdx.x];
}

// -------- Kernel 3: hard negative mining + finalize --------
#define BUFSZ 6144
extern __shared__ float sv[];  // PP floats

__device__ __forceinline__ int warp_suffix(int v, int lane) {
#pragma unroll
    for (int off = 1; off < 32; off <<= 1) {
        int t = __shfl_down_sync(0xffffffffu, v, off);
        if (lane + off < 32) v += t;
    }
    return v;
}

// two-level bin finder over hist[nb]; all threads participate.
// outputs: sB = bin containing the Krem-th largest, sK = remaining inside it
__device__ __forceinline__ void find_bin(int* hist, int nb, int Krem,
                                         int tid, int lane, int warpId,
                                         int* s_seg, int* psWstar,
                                         int* psB, int* psK) {
    int nsegs = nb >> 6;
    if (warpId < nsegs) {
        int base = warpId * 64;
        int s = hist[base + lane] + hist[base + 32 + lane];
        s = (int)__reduce_add_sync(0xffffffffu, (unsigned)s);
        if (lane == 0) s_seg[warpId] = s;
    }
    __syncthreads();
    if (tid < 32) {
        int v = (lane < nsegs) ? s_seg[lane] : 0;
        int ssum = warp_suffix(v, lane);
        unsigned bal = __ballot_sync(0xffffffffu, ssum >= Krem);
        int w = 31 - __clz(bal);
        int ssum_w = __shfl_sync(0xffffffffu, ssum, w);
        int v_w    = __shfl_sync(0xffffffffu, v, w);
        if (lane == 0) { *psWstar = w; *psK = Krem - (ssum_w - v_w); }
    }
    __syncthreads();
    if (warpId == *psWstar) {
        int base = warpId * 64;
        int K2 = *psK;
        int h1 = hist[base + 32 + lane];
        int s1 = warp_suffix(h1, lane);
        int tot1 = __shfl_sync(0xffffffffu, s1, 0);
        int bin, Kn;
        if (K2 <= tot1) {
            unsigned bal = __ballot_sync(0xffffffffu, s1 >= K2);
            int l = 31 - __clz(bal);
            bin = base + 32 + l;
            Kn = K2 - (__shfl_sync(0xffffffffu, s1, l) -
                       __shfl_sync(0xffffffffu, h1, l));
        } else {
            int K3 = K2 - tot1;
            int h0 = hist[base + lane];
            int s0 = warp_suffix(h0, lane);
            unsigned bal = __ballot_sync(0xffffffffu, s0 >= K3);
            int l = 31 - __clz(bal);
            bin = base + l;
            Kn = K3 - (__shfl_sync(0xffffffffu, s0, l) -
                       __shfl_sync(0xffffffffu, h0, l));
        }
        if (lane == 0) { *psB = bin; *psK = Kn; }
    }
    __syncthreads();
}

__global__ void mine_kernel(float* __restrict__ out) {
    const int b = blockIdx.x;
    const int tid = threadIdx.x;
    const int lane = tid & 31;
    const int warpId = tid >> 5;
    const int K = min(3 * g_npos[b], PP - 1);

    __shared__ int   hist[2048];
    __shared__ float sbuf[BUFSZ];
    __shared__ int   s_seg[32];
    __shared__ int   s_nbuf, sWstar, sB, sK, s_cnt, s_cnt2;
    __shared__ float s_sum, s_sum2;

    if (K > 0) {
        const float* vals = g_negval + (size_t)b * PP;

        // sweep 1: load sv + 2048-bin histogram of top-11 bits (fused)
        for (int i = tid; i < 2048; i += 1024) hist[i] = 0;
        if (tid == 0) {
            s_nbuf = 0; s_cnt = 0; s_sum = 0.f; s_cnt2 = 0; s_sum2 = 0.f;
        }
        __syncthreads();
        for (int p = tid; p < PP; p += 1024) {
            float v = vals[p];
            sv[p] = v;
            atomicAdd(&hist[__float_as_uint(v) >> 20], 1);
        }
        __syncthreads();

        find_bin(hist, 2048, K, tid, lane, warpId, s_seg, &sWstar, &sB, &sK);
        const int B1 = sB;
        int Krem = sK;
        __syncthreads();

        // sweep 2: sum bins > B1; collect boundary-bin elements
        int cgt = 0;
        float sum = 0.f;
        for (int p = tid; p < PP; p += 1024) {
            float v = sv[p];
            int bin = (int)(__float_as_uint(v) >> 20);
            if (bin > B1) { cgt++; sum += v; }
            else if (bin == B1) {
                int i = atomicAdd(&s_nbuf, 1);
                if (i < BUFSZ) sbuf[i] = v;
            }
        }
#pragma unroll
        for (int off = 16; off > 0; off >>= 1) {
            cgt += __shfl_down_sync(0xffffffffu, cgt, off);
            sum += __shfl_down_sync(0xffffffffu, sum, off);
        }
        if (lane == 0) { atomicAdd(&s_cnt, cgt); atomicAdd(&s_sum, sum); }
        __syncthreads();

        const int  nB = s_nbuf;
        const bool usebuf = (nB <= BUFSZ);

        // refine remaining 21 bits exactly on the boundary set
        unsigned prefix = (unsigned)B1 << 20;
        unsigned himask = 0xFFFFFFFFu << 20;
        const int shifts2[2] = {9, 0};
        const int nbs2[2]    = {2048, 512};
        for (int st = 0; st < 2; st++) {
            int shift = shifts2[st], nb = nbs2[st];
            for (int i = tid; i < nb; i += 1024) hist[i] = 0;
            __syncthreads();
            if (usebuf) {
                for (int i = tid; i < nB; i += 1024) {
                    unsigned u = __float_as_uint(sbuf[i]);
                    if ((u & himask) == prefix)
                        atomicAdd(&hist[(u >> shift) & (nb - 1)], 1);
                }
            } else {
                for (int p = tid; p < PP; p += 1024) {
                    unsigned u = __float_as_uint(sv[p]);
                    if ((u & himask) == prefix)
                        atomicAdd(&hist[(u >> shift) & (nb - 1)], 1);
                }
            }
            __syncthreads();
            find_bin(hist, nb, Krem, tid, lane, warpId, s_seg, &sWstar, &sB, &sK);
            prefix |= ((unsigned)sB) << shift;
            himask |= ((unsigned)(nb - 1)) << shift;
            Krem = sK;
            __syncthreads();
        }

        // boundary pass: strictly greater than exact threshold, within bin B1
        float t = __uint_as_float(prefix);
        int cgt2 = 0;
        float sum2 = 0.f;
        if (usebuf) {
            for (int i = tid; i < nB; i += 1024) {
                float v = sbuf[i];
                if (__float_as_uint(v) > prefix) { cgt2++; sum2 += v; }
            }
        } else {
            for (int p = tid; p < PP; p += 1024) {
                float v = sv[p];
                unsigned u = __float_as_uint(v);
                if ((int)(u >> 20) == B1 && u > prefix) { cgt2++; sum2 += v; }
            }
        }
#pragma unroll
        for (int off = 16; off > 0; off >>= 1) {
            cgt2 += __shfl_down_sync(0xffffffffu, cgt2, off);
            sum2 += __shfl_down_sync(0xffffffffu, sum2, off);
        }
        if (lane == 0) { atomicAdd(&s_cnt2, cgt2); atomicAdd(&s_sum2, sum2); }
        __syncthreads();

        if (tid == 0) {
            float total = s_sum + s_sum2 +
                          (float)(K - s_cnt - s_cnt2) * t;
            atomicAdd(&g_loss_c, total);
        }
    }

    // finalize: last block writes the output
    if (tid == 0) {
        __threadfence();
        int old = atomicAdd(&g_done, 1);
        if (old == BB - 1) {
            float lc = atomicAdd(&g_loss_c, 0.f);
            float ll = atomicAdd(&g_loss_l, 0.f);
            int   tp = atomicAdd(&g_total_pos, 0);
            float N = (float)max(tp, 1);
            out[0] = ll / N;
            out[1] = lc / N;
        }
    }
}

extern "C" void kernel_launch(void* const* d_in, const int* in_sizes, int n_in,
                              void* d_out, int out_size) {
    const float* loc_data  = (const float*)d_in[0];
    const float* conf_data = (const float*)d_in[1];
    const float* priors    = (const float*)d_in[2];
    const float* gt_boxes  = (const float*)d_in[3];
    const int*   gt_labels = (const int*)d_in[4];
    float* out = (float*)d_out;

    cudaFuncSetAttribute(mine_kernel,
                         cudaFuncAttributeMaxDynamicSharedMemorySize,
                         PP * (int)sizeof(float));

    init_kernel<<<1, BB * NOBJ>>>();
    dim3 gridI((PP + 63) / 64, BB);
    iou_kernel<<<gridI, 256>>>(priors, gt_boxes);
    dim3 gridN(PP / NLL_PRIORS, BB);
    nll_kernel<<<gridN, NLL_THREADS>>>(loc_data, conf_data, priors, gt_boxes, gt_labels);
    mine_kernel<<<BB, 1024, PP * (int)sizeof(float)>>>(out);
}